// round 1
// baseline (speedup 1.0000x reference)
#include <cuda_runtime.h>
#include <mma.h>
#include <cstdint>
#include <cstddef>

using namespace nvcuda;

// Problem dims (fixed by the dataset)
#define E_ 8
#define T_ 1024
#define D_ 2048
#define H_ 5632

// Scratch for intermediate y = silu(x@W1) * (x@W2): [E, T, H] fp32 (176 MB, BSS)
__device__ __align__(256) float g_y[(size_t)E_ * T_ * H_];

// ---------------- cp.async helpers ----------------
__device__ __forceinline__ void cp_async16(void* s, const void* g) {
    uint32_t sa = (uint32_t)__cvta_generic_to_shared(s);
    asm volatile("cp.async.cg.shared.global [%0], [%1], 16;\n" :: "r"(sa), "l"(g));
}
__device__ __forceinline__ void cp_commit() {
    asm volatile("cp.async.commit_group;\n");
}
template <int N>
__device__ __forceinline__ void cp_wait() {
    asm volatile("cp.async.wait_group %0;\n" :: "n"(N));
}

// ---------------- tiling constants ----------------
constexpr int BK   = 32;        // K-slab per stage
constexpr int BM1  = 128;       // kernel1 M tile
constexpr int BN1  = 64;        // kernel1 N tile (per gate matrix; effectively 128 wide)
constexpr int BM2  = 128;       // kernel2 M tile
constexpr int BN2  = 128;       // kernel2 N tile
constexpr int LDA  = BK  + 8;   // 40 floats  (row stride mult of 4; 32B-aligned rows)
constexpr int LDB1 = BN1 + 8;   // 72 floats
constexpr int LDB2 = BN2 + 8;   // 136 floats

constexpr size_t SMEM1 = (size_t)(2 * BM1 * LDA + 2 * 2 * BK * LDB1) * sizeof(float); // 77824 B
constexpr size_t SMEM2 = (size_t)(2 * BM2 * LDA + 2 * BK * LDB2) * sizeof(float);     // 75776 B

// =====================================================================
// Kernel 1: y[e,m,n] = silu(sum_k x[e,m,k]*W1[e,k,n]) * (sum_k x*W2)
// Grid: (H/BN1, T/BM1, E). 256 threads = 8 warps in a 4(M) x 2(N) grid.
// Warp tile: 32x32 per gate matrix -> 2x2 wmma(16x16x8,tf32) frags each.
// =====================================================================
__global__ void ffn_gate(const float* __restrict__ X,
                         const float* __restrict__ W1,
                         const float* __restrict__ W2)
{
    extern __shared__ __align__(128) float smem[];
    float* sA  = smem;                     // 2 * BM1 * LDA
    float* sB1 = sA  + 2 * BM1 * LDA;      // 2 * BK * LDB1
    float* sB2 = sB1 + 2 * BK  * LDB1;     // 2 * BK * LDB1

    const int e  = blockIdx.z;
    const int m0 = blockIdx.y * BM1;
    const int n0 = blockIdx.x * BN1;
    const float* Ax  = X  + (size_t)e * T_ * D_;
    const float* B1g = W1 + (size_t)e * D_ * H_;
    const float* B2g = W2 + (size_t)e * D_ * H_;

    const int tid  = threadIdx.x;
    const int warp = tid >> 5;
    const int wm   = warp & 3;   // 0..3
    const int wn   = warp >> 2;  // 0..1

    wmma::fragment<wmma::accumulator, 16, 16, 8, float> c1[2][2], c2[2][2];
    #pragma unroll
    for (int i = 0; i < 2; i++)
        #pragma unroll
        for (int j = 0; j < 2; j++) {
            wmma::fill_fragment(c1[i][j], 0.0f);
            wmma::fill_fragment(c2[i][j], 0.0f);
        }

    auto load_stage = [&](int buf, int kt) {
        const int k0 = kt * BK;
        float* a_dst = sA + buf * BM1 * LDA;
        // A tile: 128 rows x 32 cols = 1024 16B-chunks, 4 per thread
        #pragma unroll
        for (int i = 0; i < 4; i++) {
            int c   = tid + i * 256;
            int row = c >> 3;
            int ch  = c & 7;
            cp_async16(a_dst + row * LDA + ch * 4,
                       Ax + (size_t)(m0 + row) * D_ + k0 + ch * 4);
        }
        // B1+B2 tiles: 2 * (32 rows x 64 cols) = 1024 chunks, 4 per thread
        #pragma unroll
        for (int i = 0; i < 4; i++) {
            int c   = tid + i * 256;           // 0..1023
            int mat = c >> 9;                   // 0: W1, 1: W2
            int r   = (c >> 4) & 31;
            int ch  = c & 15;
            const float* src = (mat ? B2g : B1g) + (size_t)(k0 + r) * H_ + n0 + ch * 4;
            float* dst = (mat ? sB2 : sB1) + buf * BK * LDB1 + r * LDB1 + ch * 4;
            cp_async16(dst, src);
        }
        cp_commit();
    };

    constexpr int NK = D_ / BK;   // 64
    load_stage(0, 0);

    for (int kt = 0; kt < NK; ++kt) {
        const int buf = kt & 1;
        if (kt + 1 < NK) {
            load_stage(buf ^ 1, kt + 1);
            cp_wait<1>();
        } else {
            cp_wait<0>();
        }
        __syncthreads();

        const float* aB  = sA  + buf * BM1 * LDA  + (wm * 32) * LDA;
        const float* b1B = sB1 + buf * BK  * LDB1 + wn * 32;
        const float* b2B = sB2 + buf * BK  * LDB1 + wn * 32;

        #pragma unroll
        for (int kk = 0; kk < BK / 8; kk++) {
            wmma::fragment<wmma::matrix_a, 16, 16, 8, wmma::precision::tf32, wmma::row_major> a[2];
            wmma::fragment<wmma::matrix_b, 16, 16, 8, wmma::precision::tf32, wmma::row_major> b1[2], b2[2];
            #pragma unroll
            for (int i = 0; i < 2; i++) {
                wmma::load_matrix_sync(a[i], aB + i * 16 * LDA + kk * 8, LDA);
                #pragma unroll
                for (int t = 0; t < a[i].num_elements; t++)
                    a[i].x[t] = wmma::__float_to_tf32(a[i].x[t]);
            }
            #pragma unroll
            for (int j = 0; j < 2; j++) {
                wmma::load_matrix_sync(b1[j], b1B + kk * 8 * LDB1 + j * 16, LDB1);
                wmma::load_matrix_sync(b2[j], b2B + kk * 8 * LDB1 + j * 16, LDB1);
                #pragma unroll
                for (int t = 0; t < b1[j].num_elements; t++) {
                    b1[j].x[t] = wmma::__float_to_tf32(b1[j].x[t]);
                    b2[j].x[t] = wmma::__float_to_tf32(b2[j].x[t]);
                }
            }
            #pragma unroll
            for (int i = 0; i < 2; i++)
                #pragma unroll
                for (int j = 0; j < 2; j++) {
                    wmma::mma_sync(c1[i][j], a[i], b1[j], c1[i][j]);
                    wmma::mma_sync(c2[i][j], a[i], b2[j], c2[i][j]);
                }
        }
        __syncthreads();
    }

    // Epilogue: y = silu(y1) * y2. Same fragment layout for c1/c2 -> elementwise OK.
    float* yOut = g_y + (size_t)e * T_ * H_;
    #pragma unroll
    for (int i = 0; i < 2; i++)
        #pragma unroll
        for (int j = 0; j < 2; j++) {
            #pragma unroll
            for (int t = 0; t < c1[i][j].num_elements; t++) {
                float v1 = c1[i][j].x[t];
                float v2 = c2[i][j].x[t];
                c1[i][j].x[t] = v2 * v1 * (1.0f / (1.0f + __expf(-v1)));
            }
            wmma::store_matrix_sync(
                yOut + (size_t)(m0 + wm * 32 + i * 16) * H_ + (n0 + wn * 32 + j * 16),
                c1[i][j], H_, wmma::mem_row_major);
        }
}

// =====================================================================
// Kernel 2: out[e,m,n] = sum_k y[e,m,k] * W3[e,k,n]   (M=1024,N=2048,K=5632)
// Grid: (D/BN2, T/BM2, E). 8 warps 4(M) x 2(N); warp tile 32x64 -> 2x4 frags.
// =====================================================================
__global__ void ffn_down(const float* __restrict__ W3, float* __restrict__ Out)
{
    extern __shared__ __align__(128) float smem[];
    float* sA = smem;                   // 2 * BM2 * LDA
    float* sB = sA + 2 * BM2 * LDA;     // 2 * BK * LDB2

    const int e  = blockIdx.z;
    const int m0 = blockIdx.y * BM2;
    const int n0 = blockIdx.x * BN2;
    const float* Ay = g_y + (size_t)e * T_ * H_;
    const float* Bg = W3  + (size_t)e * H_ * D_;

    const int tid  = threadIdx.x;
    const int warp = tid >> 5;
    const int wm   = warp & 3;
    const int wn   = warp >> 2;

    wmma::fragment<wmma::accumulator, 16, 16, 8, float> c[2][4];
    #pragma unroll
    for (int i = 0; i < 2; i++)
        #pragma unroll
        for (int j = 0; j < 4; j++)
            wmma::fill_fragment(c[i][j], 0.0f);

    auto load_stage = [&](int buf, int kt) {
        const int k0 = kt * BK;
        float* a_dst = sA + buf * BM2 * LDA;
        #pragma unroll
        for (int i = 0; i < 4; i++) {
            int cdx = tid + i * 256;
            int row = cdx >> 3;
            int ch  = cdx & 7;
            cp_async16(a_dst + row * LDA + ch * 4,
                       Ay + (size_t)(m0 + row) * H_ + k0 + ch * 4);
        }
        float* b_dst = sB + buf * BK * LDB2;
        #pragma unroll
        for (int i = 0; i < 4; i++) {
            int cdx = tid + i * 256;   // 32 rows x 32 chunks = 1024
            int r   = cdx >> 5;
            int ch  = cdx & 31;
            cp_async16(b_dst + r * LDB2 + ch * 4,
                       Bg + (size_t)(k0 + r) * D_ + n0 + ch * 4);
        }
        cp_commit();
    };

    constexpr int NK = H_ / BK;   // 176
    load_stage(0, 0);

    for (int kt = 0; kt < NK; ++kt) {
        const int buf = kt & 1;
        if (kt + 1 < NK) {
            load_stage(buf ^ 1, kt + 1);
            cp_wait<1>();
        } else {
            cp_wait<0>();
        }
        __syncthreads();

        const float* aB = sA + buf * BM2 * LDA  + (wm * 32) * LDA;
        const float* bB = sB + buf * BK  * LDB2 + wn * 64;

        #pragma unroll
        for (int kk = 0; kk < BK / 8; kk++) {
            wmma::fragment<wmma::matrix_a, 16, 16, 8, wmma::precision::tf32, wmma::row_major> a[2];
            wmma::fragment<wmma::matrix_b, 16, 16, 8, wmma::precision::tf32, wmma::row_major> b[4];
            #pragma unroll
            for (int i = 0; i < 2; i++) {
                wmma::load_matrix_sync(a[i], aB + i * 16 * LDA + kk * 8, LDA);
                #pragma unroll
                for (int t = 0; t < a[i].num_elements; t++)
                    a[i].x[t] = wmma::__float_to_tf32(a[i].x[t]);
            }
            #pragma unroll
            for (int j = 0; j < 4; j++) {
                wmma::load_matrix_sync(b[j], bB + kk * 8 * LDB2 + j * 16, LDB2);
                #pragma unroll
                for (int t = 0; t < b[j].num_elements; t++)
                    b[j].x[t] = wmma::__float_to_tf32(b[j].x[t]);
            }
            #pragma unroll
            for (int i = 0; i < 2; i++)
                #pragma unroll
                for (int j = 0; j < 4; j++)
                    wmma::mma_sync(c[i][j], a[i], b[j], c[i][j]);
        }
        __syncthreads();
    }

    #pragma unroll
    for (int i = 0; i < 2; i++)
        #pragma unroll
        for (int j = 0; j < 4; j++)
            wmma::store_matrix_sync(
                Out + (size_t)e * T_ * D_ + (size_t)(m0 + wm * 32 + i * 16) * D_
                    + (n0 + wn * 64 + j * 16),
                c[i][j], D_, wmma::mem_row_major);
}

// =====================================================================
extern "C" void kernel_launch(void* const* d_in, const int* in_sizes, int n_in,
                              void* d_out, int out_size)
{
    const float* x  = (const float*)d_in[0];
    const float* w1 = (const float*)d_in[1];
    const float* w2 = (const float*)d_in[2];
    const float* w3 = (const float*)d_in[3];
    float* out = (float*)d_out;
    (void)in_sizes; (void)n_in; (void)out_size;

    // Idempotent attribute sets (no allocation, capture-safe)
    cudaFuncSetAttribute(ffn_gate, cudaFuncAttributeMaxDynamicSharedMemorySize, (int)SMEM1);
    cudaFuncSetAttribute(ffn_down, cudaFuncAttributeMaxDynamicSharedMemorySize, (int)SMEM2);

    dim3 g1(H_ / BN1, T_ / BM1, E_);   // (88, 8, 8)
    ffn_gate<<<g1, 256, SMEM1>>>(x, w1, w2);

    dim3 g2(D_ / BN2, T_ / BM2, E_);   // (16, 8, 8)
    ffn_down<<<g2, 256, SMEM2>>>(w3, out);
}

// round 3
// speedup vs baseline: 2.7673x; 2.7673x over previous
#include <cuda_runtime.h>
#include <cuda_fp16.h>
#include <mma.h>
#include <cstdint>
#include <cstddef>

using namespace nvcuda;

#define E_ 8
#define T_ 1024
#define D_ 2048
#define H_ 5632

// Intermediate y = silu(x@W1)*(x@W2): [E,T,H] fp32 (176 MB, BSS scratch)
__device__ __align__(256) float g_y[(size_t)E_ * T_ * H_];

// ---------------- helpers ----------------
union Pack4 { uint2 u; __half2 h[2]; };

__device__ __forceinline__ uint2 pack4(float4 v) {
    Pack4 p;
    p.h[0] = __floats2half2_rn(v.x, v.y);
    p.h[1] = __floats2half2_rn(v.z, v.w);
    return p.u;
}

__device__ __forceinline__ float silu_mul(float v1, float v2) {
    return v2 * v1 * (1.0f / (1.0f + __expf(-v1)));
}

// ---------------- tiling ----------------
constexpr int BM   = 256;       // CTA M tile (both kernels)
constexpr int BK   = 32;        // K slab
constexpr int BN1  = 64;        // kernel1: N per gate matrix
constexpr int BN2  = 128;       // kernel2: N tile
constexpr int LDA  = BK  + 8;   // 40 halfs (80B rows, mult of 16B)
constexpr int LDB1 = BN1 + 8;   // 72 halfs
constexpr int LDB2 = BN2 + 8;   // 136 halfs

// smem sizes (halfs)
constexpr int A_ELT  = BM * LDA;      // 10240
constexpr int B1_ELT = BK * LDB1;     // 2304
constexpr int B2_ELT = BK * LDB2;     // 4352

constexpr size_t SMEM1 = (size_t)(2 * (A_ELT + 2 * B1_ELT)) * sizeof(__half); // 59392
constexpr size_t SMEM2 = (size_t)(2 * (A_ELT + B2_ELT)) * sizeof(__half);     // 58368

// =====================================================================
// Kernel 1: y = silu(x@W1) * (x@W2)
// 512 threads, 16 warps (8M x 2N). Warp tile 32x32 per gate.
// Grid: (H/BN1, T/BM, E) = (88, 4, 8)
// =====================================================================
__global__ void __launch_bounds__(512, 1)
ffn_gate_h(const float* __restrict__ X,
           const float* __restrict__ W1,
           const float* __restrict__ W2)
{
    extern __shared__ __align__(128) __half smem[];
    __half* sA  = smem;                       // [2][BM][LDA]
    __half* sB1 = sA  + 2 * A_ELT;            // [2][BK][LDB1]
    __half* sB2 = sB1 + 2 * B1_ELT;           // [2][BK][LDB1]

    const int tid  = threadIdx.x;
    const int warp = tid >> 5;
    const int wm   = warp >> 1;   // 0..7
    const int wn   = warp & 1;    // 0..1
    const int e  = blockIdx.z;
    const int m0 = blockIdx.y * BM;
    const int n0 = blockIdx.x * BN1;
    const float* Ax  = X  + (size_t)e * T_ * D_;
    const float* B1g = W1 + (size_t)e * D_ * H_;
    const float* B2g = W2 + (size_t)e * D_ * H_;

    wmma::fragment<wmma::accumulator, 16, 16, 16, float> c1[2][2], c2[2][2];
    #pragma unroll
    for (int i = 0; i < 2; i++)
        #pragma unroll
        for (int j = 0; j < 2; j++) {
            wmma::fill_fragment(c1[i][j], 0.0f);
            wmma::fill_fragment(c2[i][j], 0.0f);
        }

    // per-thread staging (packed half)
    uint2 rA[4], rB[2];

    // A: 256 rows x 32 k = 2048 float4 chunks -> 4/thread
    const int a_row = tid >> 3;            // +128 per i (512 thr / 4 chunks... u>>3)
    const int a_ch  = tid & 7;
    // B: 2 mats x 32 rows x 16 chunks = 1024 -> 2/thread
    const int b_u0   = tid;                // i*512
    auto ldg = [&](int kt) {
        const int k0 = kt * BK;
        #pragma unroll
        for (int i = 0; i < 4; i++) {
            int row = a_row + i * 64;
            float4 v = *(const float4*)(Ax + (size_t)(m0 + row) * D_ + k0 + a_ch * 4);
            rA[i] = pack4(v);
        }
        #pragma unroll
        for (int i = 0; i < 2; i++) {
            int u = b_u0 + i * 512;
            int mat = u >> 9;
            int rem = u & 511;
            int r = rem >> 4, ch = rem & 15;
            const float* src = (mat ? B2g : B1g) + (size_t)(k0 + r) * H_ + n0 + ch * 4;
            rB[i] = pack4(*(const float4*)src);
        }
    };
    auto sts = [&](int buf) {
        __half* aD = sA + buf * A_ELT;
        #pragma unroll
        for (int i = 0; i < 4; i++) {
            int row = a_row + i * 64;
            *(uint2*)(aD + row * LDA + a_ch * 4) = rA[i];
        }
        #pragma unroll
        for (int i = 0; i < 2; i++) {
            int u = b_u0 + i * 512;
            int mat = u >> 9;
            int rem = u & 511;
            int r = rem >> 4, ch = rem & 15;
            __half* dst = (mat ? sB2 : sB1) + buf * (mat ? B1_ELT : B1_ELT) + r * LDB1 + ch * 4;
            *(uint2*)dst = rB[i];
        }
    };

    ldg(0); sts(0);
    __syncthreads();

    constexpr int NK = D_ / BK;  // 64
    for (int kt = 0; kt < NK; kt++) {
        const int buf = kt & 1;
        if (kt + 1 < NK) ldg(kt + 1);

        const __half* aB  = sA  + buf * A_ELT  + (wm * 32) * LDA;
        const __half* b1B = sB1 + buf * B1_ELT + wn * 32;
        const __half* b2B = sB2 + buf * B1_ELT + wn * 32;
        #pragma unroll
        for (int kk = 0; kk < BK / 16; kk++) {
            wmma::fragment<wmma::matrix_a, 16, 16, 16, __half, wmma::row_major> a[2];
            #pragma unroll
            for (int i = 0; i < 2; i++)
                wmma::load_matrix_sync(a[i], aB + i * 16 * LDA + kk * 16, LDA);
            {
                wmma::fragment<wmma::matrix_b, 16, 16, 16, __half, wmma::row_major> b[2];
                #pragma unroll
                for (int j = 0; j < 2; j++)
                    wmma::load_matrix_sync(b[j], b1B + kk * 16 * LDB1 + j * 16, LDB1);
                #pragma unroll
                for (int i = 0; i < 2; i++)
                    #pragma unroll
                    for (int j = 0; j < 2; j++)
                        wmma::mma_sync(c1[i][j], a[i], b[j], c1[i][j]);
            }
            {
                wmma::fragment<wmma::matrix_b, 16, 16, 16, __half, wmma::row_major> b[2];
                #pragma unroll
                for (int j = 0; j < 2; j++)
                    wmma::load_matrix_sync(b[j], b2B + kk * 16 * LDB1 + j * 16, LDB1);
                #pragma unroll
                for (int i = 0; i < 2; i++)
                    #pragma unroll
                    for (int j = 0; j < 2; j++)
                        wmma::mma_sync(c2[i][j], a[i], b[j], c2[i][j]);
            }
        }

        if (kt + 1 < NK) {
            sts(buf ^ 1);
            __syncthreads();
        }
    }

    // Epilogue: silu(c1)*c2 (same frag layout -> elementwise valid), store fp32 y
    float* yOut = g_y + (size_t)e * T_ * H_;
    #pragma unroll
    for (int i = 0; i < 2; i++)
        #pragma unroll
        for (int j = 0; j < 2; j++) {
            #pragma unroll
            for (int t = 0; t < c1[i][j].num_elements; t++)
                c1[i][j].x[t] = silu_mul(c1[i][j].x[t], c2[i][j].x[t]);
            wmma::store_matrix_sync(
                yOut + (size_t)(m0 + wm * 32 + i * 16) * H_ + (n0 + wn * 32 + j * 16),
                c1[i][j], H_, wmma::mem_row_major);
        }
}

// =====================================================================
// Kernel 2: out = y @ W3
// 512 threads, 16 warps (8M x 2N). Warp tile 32x64 (2x4 frags).
// Grid: (D/BN2, T/BM, E) = (16, 4, 8)
// =====================================================================
__global__ void __launch_bounds__(512, 1)
ffn_down_h(const float* __restrict__ W3, float* __restrict__ Out)
{
    extern __shared__ __align__(128) __half smem[];
    __half* sA = smem;                 // [2][BM][LDA]
    __half* sB = sA + 2 * A_ELT;       // [2][BK][LDB2]

    const int tid  = threadIdx.x;
    const int warp = tid >> 5;
    const int wm   = warp >> 1;
    const int wn   = warp & 1;
    const int e  = blockIdx.z;
    const int m0 = blockIdx.y * BM;
    const int n0 = blockIdx.x * BN2;
    const float* Ay = g_y + (size_t)e * T_ * H_;
    const float* Bg = W3  + (size_t)e * H_ * D_;

    wmma::fragment<wmma::accumulator, 16, 16, 16, float> c[2][4];
    #pragma unroll
    for (int i = 0; i < 2; i++)
        #pragma unroll
        for (int j = 0; j < 4; j++)
            wmma::fill_fragment(c[i][j], 0.0f);

    uint2 rA[4], rB[2];
    const int a_row = tid >> 3;
    const int a_ch  = tid & 7;
    // B: 32 rows x 32 chunks = 1024 -> 2/thread
    auto ldg = [&](int kt) {
        const int k0 = kt * BK;
        #pragma unroll
        for (int i = 0; i < 4; i++) {
            int row = a_row + i * 64;
            float4 v = *(const float4*)(Ay + (size_t)(m0 + row) * H_ + k0 + a_ch * 4);
            rA[i] = pack4(v);
        }
        #pragma unroll
        for (int i = 0; i < 2; i++) {
            int u = tid + i * 512;
            int r = u >> 5, ch = u & 31;
            rB[i] = pack4(*(const float4*)(Bg + (size_t)(k0 + r) * D_ + n0 + ch * 4));
        }
    };
    auto sts = [&](int buf) {
        __half* aD = sA + buf * A_ELT;
        #pragma unroll
        for (int i = 0; i < 4; i++) {
            int row = a_row + i * 64;
            *(uint2*)(aD + row * LDA + a_ch * 4) = rA[i];
        }
        __half* bD = sB + buf * B2_ELT;
        #pragma unroll
        for (int i = 0; i < 2; i++) {
            int u = tid + i * 512;
            int r = u >> 5, ch = u & 31;
            *(uint2*)(bD + r * LDB2 + ch * 4) = rB[i];
        }
    };

    ldg(0); sts(0);
    __syncthreads();

    constexpr int NK = H_ / BK;  // 176
    for (int kt = 0; kt < NK; kt++) {
        const int buf = kt & 1;
        if (kt + 1 < NK) ldg(kt + 1);

        const __half* aB = sA + buf * A_ELT  + (wm * 32) * LDA;
        const __half* bB = sB + buf * B2_ELT + wn * 64;
        #pragma unroll
        for (int kk = 0; kk < BK / 16; kk++) {
            wmma::fragment<wmma::matrix_a, 16, 16, 16, __half, wmma::row_major> a[2];
            #pragma unroll
            for (int i = 0; i < 2; i++)
                wmma::load_matrix_sync(a[i], aB + i * 16 * LDA + kk * 16, LDA);
            #pragma unroll
            for (int jh = 0; jh < 2; jh++) {   // B frags in halves: keep only 2 live
                wmma::fragment<wmma::matrix_b, 16, 16, 16, __half, wmma::row_major> b[2];
                #pragma unroll
                for (int j = 0; j < 2; j++)
                    wmma::load_matrix_sync(b[j], bB + kk * 16 * LDB2 + (jh * 2 + j) * 16, LDB2);
                #pragma unroll
                for (int i = 0; i < 2; i++)
                    #pragma unroll
                    for (int j = 0; j < 2; j++)
                        wmma::mma_sync(c[i][jh * 2 + j], a[i], b[j], c[i][jh * 2 + j]);
            }
        }

        if (kt + 1 < NK) {
            sts(buf ^ 1);
            __syncthreads();
        }
    }

    #pragma unroll
    for (int i = 0; i < 2; i++)
        #pragma unroll
        for (int j = 0; j < 4; j++)
            wmma::store_matrix_sync(
                Out + (size_t)e * T_ * D_
                    + (size_t)(m0 + wm * 32 + i * 16) * D_ + (n0 + wn * 64 + j * 16),
                c[i][j], D_, wmma::mem_row_major);
}

// =====================================================================
extern "C" void kernel_launch(void* const* d_in, const int* in_sizes, int n_in,
                              void* d_out, int out_size)
{
    const float* x  = (const float*)d_in[0];
    const float* w1 = (const float*)d_in[1];
    const float* w2 = (const float*)d_in[2];
    const float* w3 = (const float*)d_in[3];
    float* out = (float*)d_out;
    (void)in_sizes; (void)n_in; (void)out_size;

    cudaFuncSetAttribute(ffn_gate_h, cudaFuncAttributeMaxDynamicSharedMemorySize, (int)SMEM1);
    cudaFuncSetAttribute(ffn_down_h, cudaFuncAttributeMaxDynamicSharedMemorySize, (int)SMEM2);

    dim3 g1(H_ / BN1, T_ / BM, E_);   // (88, 4, 8)
    ffn_gate_h<<<g1, 512, SMEM1>>>(x, w1, w2);

    dim3 g2(D_ / BN2, T_ / BM, E_);   // (16, 4, 8)
    ffn_down_h<<<g2, 512, SMEM2>>>(w3, out);
}

// round 4
// speedup vs baseline: 3.7026x; 1.3380x over previous
#include <cuda_runtime.h>
#include <cuda_fp16.h>
#include <mma.h>
#include <cstdint>
#include <cstddef>

using namespace nvcuda;

#define E_ 8
#define T_ 1024
#define D_ 2048
#define H_ 5632

// fp16 copies of all GEMM operands (filled by cvt_kernel each call) + y scratch
__device__ __align__(256) __half g_hx [(size_t)E_ * T_ * D_];
__device__ __align__(256) __half g_hw1[(size_t)E_ * D_ * H_];
__device__ __align__(256) __half g_hw2[(size_t)E_ * D_ * H_];
__device__ __align__(256) __half g_hw3[(size_t)E_ * H_ * D_];
__device__ __align__(256) __half g_hy [(size_t)E_ * T_ * H_];

// ---------------- helpers ----------------
union Pack4 { uint2 u; __half2 h[2]; };
__device__ __forceinline__ uint2 pack4(float4 v) {
    Pack4 p;
    p.h[0] = __floats2half2_rn(v.x, v.y);
    p.h[1] = __floats2half2_rn(v.z, v.w);
    return p.u;
}
__device__ __forceinline__ float silu_mul(float v1, float v2) {
    return v2 * v1 * (1.0f / (1.0f + __expf(-v1)));
}
__device__ __forceinline__ void cp_async16(void* s, const void* g) {
    uint32_t sa = (uint32_t)__cvta_generic_to_shared(s);
    asm volatile("cp.async.cg.shared.global [%0], [%1], 16;" :: "r"(sa), "l"(g));
}
__device__ __forceinline__ void cp_commit() { asm volatile("cp.async.commit_group;"); }
template <int N>
__device__ __forceinline__ void cp_wait() { asm volatile("cp.async.wait_group %0;" :: "n"(N)); }

// ---------------- fp32 -> fp16 conversion pass ----------------
constexpr size_t XC = (size_t)E_ * T_ * D_ / 4;   // float4 chunks
constexpr size_t WC = (size_t)E_ * D_ * H_ / 4;
constexpr size_t TOTC = XC + 3 * WC;

__global__ void __launch_bounds__(256)
cvt_kernel(const float* __restrict__ x,  const float* __restrict__ w1,
           const float* __restrict__ w2, const float* __restrict__ w3)
{
    size_t i = (size_t)blockIdx.x * blockDim.x + threadIdx.x;
    if (i >= TOTC) return;
    const float4* src; uint2* dst; size_t off;
    if (i < XC)               { src = (const float4*)x;  dst = (uint2*)g_hx;  off = i; }
    else if (i < XC + WC)     { src = (const float4*)w1; dst = (uint2*)g_hw1; off = i - XC; }
    else if (i < XC + 2 * WC) { src = (const float4*)w2; dst = (uint2*)g_hw2; off = i - XC - WC; }
    else                      { src = (const float4*)w3; dst = (uint2*)g_hw3; off = i - XC - 2 * WC; }
    dst[off] = pack4(src[off]);
}

// ---------------- tiling ----------------
constexpr int BM  = 256;
constexpr int BK  = 64;
constexpr int BN1 = 64;    // kernel1 N per gate
constexpr int BN2 = 128;   // kernel2 N
constexpr int LDA  = BK  + 8;   // 72 halfs (144B rows)
constexpr int LDB1 = BN1 + 8;   // 72
constexpr int LDB2 = BN2 + 8;   // 136
constexpr int STG = 3;

constexpr int A_SLAB  = BM * LDA;    // 18432 halfs
constexpr int B1_SLAB = BK * LDB1;   // 4608
constexpr int B2_SLAB = BK * LDB2;   // 8704

constexpr size_t SMEM1 = (size_t)STG * (A_SLAB + 2 * B1_SLAB) * sizeof(__half); // 165888
constexpr size_t SMEM2 = (size_t)STG * (A_SLAB + B2_SLAB) * sizeof(__half);     // 162816

// =====================================================================
// Kernel 1: y = silu(x@W1) * (x@W2)   [all operands fp16, fp32 accum]
// 256 threads, 8 warps (4M x 2N). Warp tile: 64 rows x 32 cols per gate.
// Grid: (H/BN1, T/BM, E) = (88, 4, 8)
// =====================================================================
__global__ void __launch_bounds__(256, 1)
ffn_gate_h()
{
    extern __shared__ __align__(128) __half smem[];
    __half* sA  = smem;                    // [STG][A_SLAB]
    __half* sB1 = sA  + STG * A_SLAB;      // [STG][B1_SLAB]
    __half* sB2 = sB1 + STG * B1_SLAB;     // [STG][B1_SLAB]

    const int tid  = threadIdx.x;
    const int warp = tid >> 5;
    const int lane = tid & 31;
    const int wm   = warp >> 1;   // 0..3
    const int wn   = warp & 1;    // 0..1
    const int e  = blockIdx.z;
    const int m0 = blockIdx.y * BM;
    const int n0 = blockIdx.x * BN1;
    const __half* Ax  = g_hx  + (size_t)e * T_ * D_;
    const __half* B1g = g_hw1 + (size_t)e * D_ * H_;
    const __half* B2g = g_hw2 + (size_t)e * D_ * H_;

    wmma::fragment<wmma::accumulator, 16, 16, 16, float> c1[4][2], c2[4][2];
    #pragma unroll
    for (int i = 0; i < 4; i++)
        #pragma unroll
        for (int j = 0; j < 2; j++) {
            wmma::fill_fragment(c1[i][j], 0.0f);
            wmma::fill_fragment(c2[i][j], 0.0f);
        }

    auto load = [&](int s, int kt) {
        const int k0 = kt * BK;
        // A: 256 rows x 8 chunks(16B) = 2048 -> 8/thread
        #pragma unroll
        for (int i = 0; i < 8; i++) {
            int u = tid + i * 256;
            int row = u >> 3, ch = u & 7;
            cp_async16(sA + s * A_SLAB + row * LDA + ch * 8,
                       Ax + (size_t)(m0 + row) * D_ + k0 + ch * 8);
        }
        // B1+B2: 2 x 64 rows x 8 chunks = 1024 -> 4/thread
        #pragma unroll
        for (int i = 0; i < 4; i++) {
            int u = tid + i * 256;
            int mat = u >> 9;
            int rem = u & 511;
            int r = rem >> 3, ch = rem & 7;
            const __half* src = (mat ? B2g : B1g) + (size_t)(k0 + r) * H_ + n0 + ch * 8;
            __half* dst = (mat ? sB2 : sB1) + s * B1_SLAB + r * LDB1 + ch * 8;
            cp_async16(dst, src);
        }
        cp_commit();
    };

    constexpr int NK = D_ / BK;  // 32
    load(0, 0);
    load(1, 1);

    for (int kt = 0; kt < NK; kt++) {
        const int s = kt % 3;
        cp_wait<1>();
        __syncthreads();
        if (kt + 2 < NK) load((kt + 2) % 3, kt + 2);

        const __half* aW  = sA  + s * A_SLAB  + (wm * 64) * LDA;
        const __half* b1W = sB1 + s * B1_SLAB + wn * 32;
        const __half* b2W = sB2 + s * B1_SLAB + wn * 32;
        #pragma unroll
        for (int kk = 0; kk < BK / 16; kk++) {
            wmma::fragment<wmma::matrix_a, 16, 16, 16, __half, wmma::row_major> a[4];
            #pragma unroll
            for (int i = 0; i < 4; i++)
                wmma::load_matrix_sync(a[i], aW + i * 16 * LDA + kk * 16, LDA);
            {
                wmma::fragment<wmma::matrix_b, 16, 16, 16, __half, wmma::row_major> b[2];
                #pragma unroll
                for (int j = 0; j < 2; j++)
                    wmma::load_matrix_sync(b[j], b1W + kk * 16 * LDB1 + j * 16, LDB1);
                #pragma unroll
                for (int i = 0; i < 4; i++)
                    #pragma unroll
                    for (int j = 0; j < 2; j++)
                        wmma::mma_sync(c1[i][j], a[i], b[j], c1[i][j]);
            }
            {
                wmma::fragment<wmma::matrix_b, 16, 16, 16, __half, wmma::row_major> b[2];
                #pragma unroll
                for (int j = 0; j < 2; j++)
                    wmma::load_matrix_sync(b[j], b2W + kk * 16 * LDB1 + j * 16, LDB1);
                #pragma unroll
                for (int i = 0; i < 4; i++)
                    #pragma unroll
                    for (int j = 0; j < 2; j++)
                        wmma::mma_sync(c2[i][j], a[i], b[j], c2[i][j]);
            }
        }
        __syncthreads();
    }

    // Epilogue: silu(c1)*c2 -> fp16 y. Stage per-warp 64x32 fp32 patch in smem.
    float* pw = (float*)smem + warp * (64 * 32);
    #pragma unroll
    for (int i = 0; i < 4; i++)
        #pragma unroll
        for (int j = 0; j < 2; j++) {
            #pragma unroll
            for (int t = 0; t < c1[i][j].num_elements; t++)
                c1[i][j].x[t] = silu_mul(c1[i][j].x[t], c2[i][j].x[t]);
            wmma::store_matrix_sync(pw + i * 16 * 32 + j * 16, c1[i][j], 32,
                                    wmma::mem_row_major);
        }
    __syncwarp();
    __half* yb = g_hy + (size_t)e * T_ * H_ + (size_t)(m0 + wm * 64) * H_ + n0 + wn * 32;
    #pragma unroll
    for (int r2 = 0; r2 < 32; r2++) {
        int row  = r2 * 2 + (lane >> 4);
        int col2 = lane & 15;
        float2 v = *(float2*)(pw + row * 32 + col2 * 2);
        *(__half2*)(yb + (size_t)row * H_ + col2 * 2) = __floats2half2_rn(v.x, v.y);
    }
}

// =====================================================================
// Kernel 2: out = y @ W3  (fp16 in, fp32 accum/out)
// 256 threads, 8 warps (4M x 2N). Warp tile 64x64.
// Grid: (D/BN2, T/BM, E) = (16, 4, 8)
// =====================================================================
__global__ void __launch_bounds__(256, 1)
ffn_down_h(float* __restrict__ Out)
{
    extern __shared__ __align__(128) __half smem[];
    __half* sA = smem;                 // [STG][A_SLAB]
    __half* sB = sA + STG * A_SLAB;    // [STG][B2_SLAB]

    const int tid  = threadIdx.x;
    const int warp = tid >> 5;
    const int wm   = warp >> 1;
    const int wn   = warp & 1;
    const int e  = blockIdx.z;
    const int m0 = blockIdx.y * BM;
    const int n0 = blockIdx.x * BN2;
    const __half* Ay = g_hy  + (size_t)e * T_ * H_;
    const __half* Bg = g_hw3 + (size_t)e * H_ * D_;

    wmma::fragment<wmma::accumulator, 16, 16, 16, float> c[4][4];
    #pragma unroll
    for (int i = 0; i < 4; i++)
        #pragma unroll
        for (int j = 0; j < 4; j++)
            wmma::fill_fragment(c[i][j], 0.0f);

    auto load = [&](int s, int kt) {
        const int k0 = kt * BK;
        #pragma unroll
        for (int i = 0; i < 8; i++) {
            int u = tid + i * 256;
            int row = u >> 3, ch = u & 7;
            cp_async16(sA + s * A_SLAB + row * LDA + ch * 8,
                       Ay + (size_t)(m0 + row) * H_ + k0 + ch * 8);
        }
        // B: 64 rows x 16 chunks = 1024 -> 4/thread
        #pragma unroll
        for (int i = 0; i < 4; i++) {
            int u = tid + i * 256;
            int r = u >> 4, ch = u & 15;
            cp_async16(sB + s * B2_SLAB + r * LDB2 + ch * 8,
                       Bg + (size_t)(k0 + r) * D_ + n0 + ch * 8);
        }
        cp_commit();
    };

    constexpr int NK = H_ / BK;  // 88
    load(0, 0);
    load(1, 1);

    for (int kt = 0; kt < NK; kt++) {
        const int s = kt % 3;
        cp_wait<1>();
        __syncthreads();
        if (kt + 2 < NK) load((kt + 2) % 3, kt + 2);

        const __half* aW = sA + s * A_SLAB  + (wm * 64) * LDA;
        const __half* bW = sB + s * B2_SLAB + wn * 64;
        #pragma unroll
        for (int kk = 0; kk < BK / 16; kk++) {
            wmma::fragment<wmma::matrix_a, 16, 16, 16, __half, wmma::row_major> a[4];
            #pragma unroll
            for (int i = 0; i < 4; i++)
                wmma::load_matrix_sync(a[i], aW + i * 16 * LDA + kk * 16, LDA);
            #pragma unroll
            for (int jh = 0; jh < 2; jh++) {
                wmma::fragment<wmma::matrix_b, 16, 16, 16, __half, wmma::row_major> b[2];
                #pragma unroll
                for (int j = 0; j < 2; j++)
                    wmma::load_matrix_sync(b[j], bW + kk * 16 * LDB2 + (jh * 2 + j) * 16, LDB2);
                #pragma unroll
                for (int i = 0; i < 4; i++)
                    #pragma unroll
                    for (int j = 0; j < 2; j++)
                        wmma::mma_sync(c[i][jh * 2 + j], a[i], b[j], c[i][jh * 2 + j]);
            }
        }
        __syncthreads();
    }

    #pragma unroll
    for (int i = 0; i < 4; i++)
        #pragma unroll
        for (int j = 0; j < 4; j++)
            wmma::store_matrix_sync(
                Out + (size_t)e * T_ * D_
                    + (size_t)(m0 + wm * 64 + i * 16) * D_ + (n0 + wn * 64 + j * 16),
                c[i][j], D_, wmma::mem_row_major);
}

// =====================================================================
extern "C" void kernel_launch(void* const* d_in, const int* in_sizes, int n_in,
                              void* d_out, int out_size)
{
    const float* x  = (const float*)d_in[0];
    const float* w1 = (const float*)d_in[1];
    const float* w2 = (const float*)d_in[2];
    const float* w3 = (const float*)d_in[3];
    float* out = (float*)d_out;
    (void)in_sizes; (void)n_in; (void)out_size;

    cudaFuncSetAttribute(ffn_gate_h, cudaFuncAttributeMaxDynamicSharedMemorySize, (int)SMEM1);
    cudaFuncSetAttribute(ffn_down_h, cudaFuncAttributeMaxDynamicSharedMemorySize, (int)SMEM2);

    cvt_kernel<<<(int)((TOTC + 255) / 256), 256>>>(x, w1, w2, w3);

    dim3 g1(H_ / BN1, T_ / BM, E_);   // (88, 4, 8)
    ffn_gate_h<<<g1, 256, SMEM1>>>();

    dim3 g2(D_ / BN2, T_ / BM, E_);   // (16, 4, 8)
    ffn_down_h<<<g2, 256, SMEM2>>>(out);
}

// round 5
// speedup vs baseline: 3.8982x; 1.0528x over previous
#include <cuda_runtime.h>
#include <cuda_fp16.h>
#include <mma.h>
#include <cstdint>
#include <cstddef>

using namespace nvcuda;

#define E_ 8
#define T_ 1024
#define D_ 2048
#define H_ 5632

// fp16 copies of all GEMM operands (filled by cvt_kernel each call) + y scratch
__device__ __align__(256) __half g_hx [(size_t)E_ * T_ * D_];
__device__ __align__(256) __half g_hw1[(size_t)E_ * D_ * H_];
__device__ __align__(256) __half g_hw2[(size_t)E_ * D_ * H_];
__device__ __align__(256) __half g_hw3[(size_t)E_ * H_ * D_];
__device__ __align__(256) __half g_hy [(size_t)E_ * T_ * H_];

// ---------------- helpers ----------------
union Pack4 { uint2 u; __half2 h[2]; };
__device__ __forceinline__ uint2 pack4(float4 v) {
    Pack4 p;
    p.h[0] = __floats2half2_rn(v.x, v.y);
    p.h[1] = __floats2half2_rn(v.z, v.w);
    return p.u;
}
__device__ __forceinline__ float silu_mul(float v1, float v2) {
    return v2 * v1 * (1.0f / (1.0f + __expf(-v1)));
}
__device__ __forceinline__ void cp_async16(void* s, const void* g) {
    uint32_t sa = (uint32_t)__cvta_generic_to_shared(s);
    asm volatile("cp.async.cg.shared.global [%0], [%1], 16;" :: "r"(sa), "l"(g));
}
__device__ __forceinline__ void cp_commit() { asm volatile("cp.async.commit_group;"); }
template <int N>
__device__ __forceinline__ void cp_wait() { asm volatile("cp.async.wait_group %0;" :: "n"(N)); }

// ---------------- fp32 -> fp16 conversion pass ----------------
constexpr size_t XC = (size_t)E_ * T_ * D_ / 4;   // float4 chunks
constexpr size_t WC = (size_t)E_ * D_ * H_ / 4;
constexpr size_t TOTC = XC + 3 * WC;

__global__ void __launch_bounds__(256)
cvt_kernel(const float* __restrict__ x,  const float* __restrict__ w1,
           const float* __restrict__ w2, const float* __restrict__ w3)
{
    size_t i = (size_t)blockIdx.x * blockDim.x + threadIdx.x;
    if (i >= TOTC) return;
    const float4* src; uint2* dst; size_t off;
    if (i < XC)               { src = (const float4*)x;  dst = (uint2*)g_hx;  off = i; }
    else if (i < XC + WC)     { src = (const float4*)w1; dst = (uint2*)g_hw1; off = i - XC; }
    else if (i < XC + 2 * WC) { src = (const float4*)w2; dst = (uint2*)g_hw2; off = i - XC - WC; }
    else                      { src = (const float4*)w3; dst = (uint2*)g_hw3; off = i - XC - 2 * WC; }
    dst[off] = pack4(src[off]);
}

// ---------------- tiling ----------------
constexpr int BM  = 256;
constexpr int BK  = 64;
constexpr int BN1 = 64;    // kernel1 N per gate
constexpr int BN2 = 128;   // kernel2 N
constexpr int LDA  = BK  + 8;   // 72 halfs (144B rows)
constexpr int LDB1 = BN1 + 8;   // 72
constexpr int LDB2 = BN2 + 8;   // 136
constexpr int STG = 4;

constexpr int A_SLAB  = BM * LDA;    // 18432 halfs
constexpr int B1_SLAB = BK * LDB1;   // 4608
constexpr int B2_SLAB = BK * LDB2;   // 8704

constexpr size_t SMEM1 = (size_t)STG * (A_SLAB + 2 * B1_SLAB) * sizeof(__half); // 221184
constexpr size_t SMEM2 = (size_t)STG * (A_SLAB + B2_SLAB) * sizeof(__half);     // 217088

// =====================================================================
// Kernel 1: y = silu(x@W1) * (x@W2)
// 256 threads, 8 warps (4M x 2N). Warp tile: 64 x 32 per gate.
// Grid: (T/BM, H/BN1, E) = (4, 88, 8)  -- M fastest for L2 weight reuse
// =====================================================================
__global__ void __launch_bounds__(256, 1)
ffn_gate_h()
{
    extern __shared__ __align__(128) __half smem[];
    __half* sA  = smem;                    // [STG][A_SLAB]
    __half* sB1 = sA  + STG * A_SLAB;      // [STG][B1_SLAB]
    __half* sB2 = sB1 + STG * B1_SLAB;     // [STG][B1_SLAB]

    const int tid  = threadIdx.x;
    const int warp = tid >> 5;
    const int lane = tid & 31;
    const int wm   = warp >> 1;   // 0..3
    const int wn   = warp & 1;    // 0..1
    const int e  = blockIdx.z;
    const int m0 = blockIdx.x * BM;
    const int n0 = blockIdx.y * BN1;
    const __half* Ax  = g_hx  + (size_t)e * T_ * D_;
    const __half* B1g = g_hw1 + (size_t)e * D_ * H_;
    const __half* B2g = g_hw2 + (size_t)e * D_ * H_;

    wmma::fragment<wmma::accumulator, 16, 16, 16, float> c1[4][2], c2[4][2];
    #pragma unroll
    for (int i = 0; i < 4; i++)
        #pragma unroll
        for (int j = 0; j < 2; j++) {
            wmma::fill_fragment(c1[i][j], 0.0f);
            wmma::fill_fragment(c2[i][j], 0.0f);
        }

    auto load = [&](int s, int kt) {
        const int k0 = kt * BK;
        // A: 256 rows x 8 chunks(16B) = 2048 -> 8/thread
        #pragma unroll
        for (int i = 0; i < 8; i++) {
            int u = tid + i * 256;
            int row = u >> 3, ch = u & 7;
            cp_async16(sA + s * A_SLAB + row * LDA + ch * 8,
                       Ax + (size_t)(m0 + row) * D_ + k0 + ch * 8);
        }
        // B1+B2: 2 x 64 rows x 8 chunks = 1024 -> 4/thread
        #pragma unroll
        for (int i = 0; i < 4; i++) {
            int u = tid + i * 256;
            int mat = u >> 9;
            int rem = u & 511;
            int r = rem >> 3, ch = rem & 7;
            const __half* src = (mat ? B2g : B1g) + (size_t)(k0 + r) * H_ + n0 + ch * 8;
            __half* dst = (mat ? sB2 : sB1) + s * B1_SLAB + r * LDB1 + ch * 8;
            cp_async16(dst, src);
        }
        cp_commit();
    };

    constexpr int NK = D_ / BK;  // 32
    load(0, 0);
    load(1, 1);
    load(2, 2);

    for (int kt = 0; kt < NK; kt++) {
        const int s = kt & 3;
        cp_wait<2>();
        __syncthreads();
        if (kt + 3 < NK) load((kt + 3) & 3, kt + 3);

        const __half* aW  = sA  + s * A_SLAB  + (wm * 64) * LDA;
        const __half* b1W = sB1 + s * B1_SLAB + wn * 32;
        const __half* b2W = sB2 + s * B1_SLAB + wn * 32;
        #pragma unroll
        for (int kk = 0; kk < BK / 16; kk++) {
            wmma::fragment<wmma::matrix_a, 16, 16, 16, __half, wmma::row_major> a[4];
            #pragma unroll
            for (int i = 0; i < 4; i++)
                wmma::load_matrix_sync(a[i], aW + i * 16 * LDA + kk * 16, LDA);
            {
                wmma::fragment<wmma::matrix_b, 16, 16, 16, __half, wmma::row_major> b[2];
                #pragma unroll
                for (int j = 0; j < 2; j++)
                    wmma::load_matrix_sync(b[j], b1W + kk * 16 * LDB1 + j * 16, LDB1);
                #pragma unroll
                for (int i = 0; i < 4; i++)
                    #pragma unroll
                    for (int j = 0; j < 2; j++)
                        wmma::mma_sync(c1[i][j], a[i], b[j], c1[i][j]);
            }
            {
                wmma::fragment<wmma::matrix_b, 16, 16, 16, __half, wmma::row_major> b[2];
                #pragma unroll
                for (int j = 0; j < 2; j++)
                    wmma::load_matrix_sync(b[j], b2W + kk * 16 * LDB1 + j * 16, LDB1);
                #pragma unroll
                for (int i = 0; i < 4; i++)
                    #pragma unroll
                    for (int j = 0; j < 2; j++)
                        wmma::mma_sync(c2[i][j], a[i], b[j], c2[i][j]);
            }
        }
        // NOTE: no bottom barrier — the top sync of the next iteration orders
        // this stage's last consumption before any cp.async overwrites it.
    }

    // Epilogue: silu(c1)*c2 -> fp16 y. Stage per-warp 64x32 fp32 patch in smem.
    __syncthreads();
    float* pw = (float*)smem + warp * (64 * 32);
    #pragma unroll
    for (int i = 0; i < 4; i++)
        #pragma unroll
        for (int j = 0; j < 2; j++) {
            #pragma unroll
            for (int t = 0; t < c1[i][j].num_elements; t++)
                c1[i][j].x[t] = silu_mul(c1[i][j].x[t], c2[i][j].x[t]);
            wmma::store_matrix_sync(pw + i * 16 * 32 + j * 16, c1[i][j], 32,
                                    wmma::mem_row_major);
        }
    __syncwarp();
    __half* yb = g_hy + (size_t)e * T_ * H_ + (size_t)(m0 + wm * 64) * H_ + n0 + wn * 32;
    #pragma unroll
    for (int r2 = 0; r2 < 32; r2++) {
        int row  = r2 * 2 + (lane >> 4);
        int col2 = lane & 15;
        float2 v = *(float2*)(pw + row * 32 + col2 * 2);
        *(__half2*)(yb + (size_t)row * H_ + col2 * 2) = __floats2half2_rn(v.x, v.y);
    }
}

// =====================================================================
// Kernel 2: out = y @ W3
// 256 threads, 8 warps (4M x 2N). Warp tile 64x64.
// Grid: (T/BM, D/BN2, E) = (4, 16, 8)  -- M fastest for L2 weight reuse
// =====================================================================
__global__ void __launch_bounds__(256, 1)
ffn_down_h(float* __restrict__ Out)
{
    extern __shared__ __align__(128) __half smem[];
    __half* sA = smem;                 // [STG][A_SLAB]
    __half* sB = sA + STG * A_SLAB;    // [STG][B2_SLAB]

    const int tid  = threadIdx.x;
    const int warp = tid >> 5;
    const int wm   = warp >> 1;
    const int wn   = warp & 1;
    const int e  = blockIdx.z;
    const int m0 = blockIdx.x * BM;
    const int n0 = blockIdx.y * BN2;
    const __half* Ay = g_hy  + (size_t)e * T_ * H_;
    const __half* Bg = g_hw3 + (size_t)e * H_ * D_;

    wmma::fragment<wmma::accumulator, 16, 16, 16, float> c[4][4];
    #pragma unroll
    for (int i = 0; i < 4; i++)
        #pragma unroll
        for (int j = 0; j < 4; j++)
            wmma::fill_fragment(c[i][j], 0.0f);

    auto load = [&](int s, int kt) {
        const int k0 = kt * BK;
        #pragma unroll
        for (int i = 0; i < 8; i++) {
            int u = tid + i * 256;
            int row = u >> 3, ch = u & 7;
            cp_async16(sA + s * A_SLAB + row * LDA + ch * 8,
                       Ay + (size_t)(m0 + row) * H_ + k0 + ch * 8);
        }
        // B: 64 rows x 16 chunks = 1024 -> 4/thread
        #pragma unroll
        for (int i = 0; i < 4; i++) {
            int u = tid + i * 256;
            int r = u >> 4, ch = u & 15;
            cp_async16(sB + s * B2_SLAB + r * LDB2 + ch * 8,
                       Bg + (size_t)(k0 + r) * D_ + n0 + ch * 8);
        }
        cp_commit();
    };

    constexpr int NK = H_ / BK;  // 88
    load(0, 0);
    load(1, 1);
    load(2, 2);

    for (int kt = 0; kt < NK; kt++) {
        const int s = kt & 3;
        cp_wait<2>();
        __syncthreads();
        if (kt + 3 < NK) load((kt + 3) & 3, kt + 3);

        const __half* aW = sA + s * A_SLAB  + (wm * 64) * LDA;
        const __half* bW = sB + s * B2_SLAB + wn * 64;
        #pragma unroll
        for (int kk = 0; kk < BK / 16; kk++) {
            wmma::fragment<wmma::matrix_a, 16, 16, 16, __half, wmma::row_major> a[4];
            #pragma unroll
            for (int i = 0; i < 4; i++)
                wmma::load_matrix_sync(a[i], aW + i * 16 * LDA + kk * 16, LDA);
            #pragma unroll
            for (int jh = 0; jh < 2; jh++) {
                wmma::fragment<wmma::matrix_b, 16, 16, 16, __half, wmma::row_major> b[2];
                #pragma unroll
                for (int j = 0; j < 2; j++)
                    wmma::load_matrix_sync(b[j], bW + kk * 16 * LDB2 + (jh * 2 + j) * 16, LDB2);
                #pragma unroll
                for (int i = 0; i < 4; i++)
                    #pragma unroll
                    for (int j = 0; j < 2; j++)
                        wmma::mma_sync(c[i][jh * 2 + j], a[i], b[j], c[i][jh * 2 + j]);
            }
        }
        // no bottom barrier (see kernel 1)
    }

    #pragma unroll
    for (int i = 0; i < 4; i++)
        #pragma unroll
        for (int j = 0; j < 4; j++)
            wmma::store_matrix_sync(
                Out + (size_t)e * T_ * D_
                    + (size_t)(m0 + wm * 64 + i * 16) * D_ + (n0 + wn * 64 + j * 16),
                c[i][j], D_, wmma::mem_row_major);
}

// =====================================================================
extern "C" void kernel_launch(void* const* d_in, const int* in_sizes, int n_in,
                              void* d_out, int out_size)
{
    const float* x  = (const float*)d_in[0];
    const float* w1 = (const float*)d_in[1];
    const float* w2 = (const float*)d_in[2];
    const float* w3 = (const float*)d_in[3];
    float* out = (float*)d_out;
    (void)in_sizes; (void)n_in; (void)out_size;

    cudaFuncSetAttribute(ffn_gate_h, cudaFuncAttributeMaxDynamicSharedMemorySize, (int)SMEM1);
    cudaFuncSetAttribute(ffn_down_h, cudaFuncAttributeMaxDynamicSharedMemorySize, (int)SMEM2);

    cvt_kernel<<<(int)((TOTC + 255) / 256), 256>>>(x, w1, w2, w3);

    dim3 g1(T_ / BM, H_ / BN1, E_);   // (4, 88, 8) -- M fastest
    ffn_gate_h<<<g1, 256, SMEM1>>>();

    dim3 g2(T_ / BM, D_ / BN2, E_);   // (4, 16, 8) -- M fastest
    ffn_down_h<<<g2, 256, SMEM2>>>(out);
}